// round 8
// baseline (speedup 1.0000x reference)
#include <cuda_runtime.h>
#include <cuda_bf16.h>
#include <math.h>
#include <stdint.h>

#define HC   128
#define NH   8
#define COLS 256
#define MAXN 50000
#define MAXM 400000
#define TM   128   // edges per tile

typedef unsigned long long ull;

// Scratch (device globals — no allocation allowed)
__device__ float g_q[MAXN * HC];
__device__ float g_k[MAXN * HC];
__device__ float g_v[MAXN * HC];
__device__ float g_agg[MAXN * HC];
__device__ float g_segmax[MAXN * NH];
__device__ float g_denom[MAXN * NH];
__device__ float g_ex[MAXM * NH];
// CSR scratch
__device__ int   g_count[MAXN];
__device__ int   g_rows[MAXN + 1];
__device__ int   g_cursor[MAXN];
__device__ int   g_elist[MAXM];
__device__ int   g_bsum[256];
__device__ int   g_bsumx[256];

__device__ __forceinline__ void atomicMaxFloat(float* addr, float val) {
    if (val >= 0.0f) atomicMax((int*)addr, __float_as_int(val));
    else             atomicMin((unsigned int*)addr, __float_as_uint(val));
}

__device__ __forceinline__ uint32_t smem_u32(const void* p) {
    uint32_t a;
    asm("{ .reg .u64 t; cvta.to.shared.u64 t, %1; cvt.u32.u64 %0, t; }"
        : "=r"(a) : "l"(p));
    return a;
}

// ---------------------------------------------------------------------------
// mma.sync / ldmatrix (base PTX ISA — valid for compute_103)
// ---------------------------------------------------------------------------
#define MMA_BF16(c, a, b) \
    asm volatile( \
        "mma.sync.aligned.m16n8k16.row.col.f32.bf16.bf16.f32 " \
        "{%0,%1,%2,%3}, {%4,%5,%6,%7}, {%8,%9}, {%0,%1,%2,%3};" \
        : "+f"((c)[0]), "+f"((c)[1]), "+f"((c)[2]), "+f"((c)[3]) \
        : "r"((a)[0]), "r"((a)[1]), "r"((a)[2]), "r"((a)[3]), \
          "r"((b)[0]), "r"((b)[1]))

#define LDSM_X4(r, addr) \
    asm volatile("ldmatrix.sync.aligned.m8n8.x4.shared.b16 {%0,%1,%2,%3}, [%4];" \
        : "=r"((r)[0]), "=r"((r)[1]), "=r"((r)[2]), "=r"((r)[3]) : "r"(addr))

// Row pitch 136 bf16 = 272 B (17x16B, conflict-free ldmatrix).
#define PITCHB  272

__device__ __forceinline__ void split_store(char* hi_p, char* lo_p, float2 x) {
    __nv_bfloat162 hi2 = __floats2bfloat162_rn(x.x, x.y);
    float r0 = x.x - __bfloat162float(hi2.x);
    float r1 = x.y - __bfloat162float(hi2.y);
    __nv_bfloat162 lo2 = __floats2bfloat162_rn(r0, r1);
    *(uint32_t*)hi_p = *(uint32_t*)&hi2;
    *(uint32_t*)lo_p = *(uint32_t*)&lo2;
}

// ---------------- SMEM layouts ----------------
#define SM_WB   0
#define SM_WB_S 69632
#define SM_WB_P 34816
#define SM_A    139264
#define SM_A_S  34816
#define SM_PART 208896
#define SM_QI   225280
#define SM_KI   225792
#define SM_EDGE_TOTAL 226304
#define PM_A    0
#define PM_S    34816
#define PM_W    69632
#define PM_TOTAL 139264

// ---------------------------------------------------------------------------
// Init: segmax=-inf, denom=0, count=0
// ---------------------------------------------------------------------------
__global__ void k_init(int n) {
    int i = blockIdx.x * blockDim.x + threadIdx.x;
    if (i < n * NH) {
        ((unsigned int*)g_segmax)[i] = 0xFF800000u;  // -inf
        g_denom[i] = 0.0f;
    }
    if (i < n) g_count[i] = 0;
}

// ---------------------------------------------------------------------------
// CSR build
// ---------------------------------------------------------------------------
__global__ void k_hist(const int* __restrict__ qidx, int m) {
    int i = blockIdx.x * blockDim.x + threadIdx.x;
    if (i < m) atomicAdd(&g_count[qidx[i]], 1);
}

// per-block inclusive scan of 256-chunks; writes exclusive, block sums to g_bsum
__global__ void k_scan1(int n) {
    __shared__ int s[256];
    int t = threadIdx.x;
    int idx = blockIdx.x * 256 + t;
    int v = (idx < n) ? g_count[idx] : 0;
    s[t] = v;
    __syncthreads();
    int acc = v;
#pragma unroll
    for (int off = 1; off < 256; off <<= 1) {
        int add = (t >= off) ? s[t - off] : 0;
        __syncthreads();
        acc += add;
        s[t] = acc;
        __syncthreads();
    }
    if (idx <= n) g_rows[idx] = acc - v;   // exclusive within block
    if (t == 255) g_bsum[blockIdx.x] = acc;
}

// single-block exclusive scan of block sums
__global__ void k_scan2(int nb) {
    __shared__ int s[256];
    int t = threadIdx.x;
    int v = (t < nb) ? g_bsum[t] : 0;
    s[t] = v;
    __syncthreads();
    int acc = v;
#pragma unroll
    for (int off = 1; off < 256; off <<= 1) {
        int add = (t >= off) ? s[t - off] : 0;
        __syncthreads();
        acc += add;
        s[t] = acc;
        __syncthreads();
    }
    g_bsumx[t] = acc - v;
}

__global__ void k_scan3(int n, int m) {
    int i = blockIdx.x * blockDim.x + threadIdx.x;
    if (i < n) {
        int rs = g_rows[i] + g_bsumx[i >> 8];
        g_rows[i] = rs;
        g_cursor[i] = rs;
    }
    if (i == 0) g_rows[n] = m;
}

__global__ void k_fill(const int* __restrict__ qidx, int m) {
    int i = blockIdx.x * blockDim.x + threadIdx.x;
    if (i < m) {
        int pos = atomicAdd(&g_cursor[qidx[i]], 1);
        g_elist[pos] = i;
    }
}

// ---------------------------------------------------------------------------
// Projection GEMMs via bf16 split-3 mma (validated)
// ---------------------------------------------------------------------------
__global__ __launch_bounds__(512, 1) void k_proj_mma(
    const float* __restrict__ query, const float* __restrict__ key,
    const float* __restrict__ Wq, const float* __restrict__ Wkv, int n)
{
    extern __shared__ char smem[];
    uint32_t sbase = smem_u32(smem);

    int tid  = threadIdx.x;
    int warp = tid >> 5;
    int lane = tid & 31;
    int wm   = warp >> 2;
    int wn   = warp & 3;
    int g    = lane >> 2;
    int t4   = lane & 3;

    uint32_t aoff = (uint32_t)(((lane & 7) + 8 * ((lane >> 3) & 1)) * PITCHB
                               + ((lane >> 4) & 1) * 16);
    uint32_t boff = (uint32_t)(((lane & 7) + 8 * ((lane >> 4) & 1)) * PITCHB
                               + ((lane >> 3) & 1) * 16);
    uint32_t a_base = sbase + PM_A + (uint32_t)(wm * 32) * PITCHB + aoff;
    uint32_t b_base = sbase + PM_W + (uint32_t)(wn * 32) * PITCHB + boff;

    int ntiles = (n + TM - 1) / TM;
    for (int tile = blockIdx.x; tile < ntiles; tile += gridDim.x) {
        int nb = tile * TM;

#pragma unroll 1
        for (int chunk = 0; chunk < 3; chunk++) {
            __syncthreads();

            if (chunk < 2) {
                const float* Asrc = (chunk == 0) ? query : key;
                for (int i = tid; i < TM * 64; i += 512) {
                    int r = i >> 6, cp = i & 63;
                    int row = nb + r;
                    float2 x = (row < n) ? ((const float2*)Asrc)[(size_t)row * 64 + cp]
                                         : make_float2(0.f, 0.f);
                    size_t off = (size_t)r * PITCHB + (size_t)cp * 4;
                    split_store(smem + PM_A + off, smem + PM_A + PM_S + off, x);
                }
            }
            {
                const float* Wsrc = (chunk == 0) ? Wq : Wkv;
                int ldW = (chunk == 0) ? HC : COLS;
                int cb  = (chunk == 2) ? HC : 0;
                for (int i = tid; i < 128 * 64; i += 512) {
                    int nc = i >> 6, kp = i & 63;
                    float2 w = make_float2(Wsrc[(2 * kp)     * ldW + cb + nc],
                                           Wsrc[(2 * kp + 1) * ldW + cb + nc]);
                    size_t off = (size_t)nc * PITCHB + (size_t)kp * 4;
                    split_store(smem + PM_W + off, smem + PM_W + PM_S + off, w);
                }
            }
            __syncthreads();

            float acc[2][4][4];
#pragma unroll
            for (int mt = 0; mt < 2; mt++)
#pragma unroll
                for (int nt = 0; nt < 4; nt++)
#pragma unroll
                    for (int el = 0; el < 4; el++) acc[mt][nt][el] = 0.f;

#pragma unroll 2
            for (int ks = 0; ks < 8; ks++) {
                uint32_t bh[4][2], bl[4][2], ah[2][4], al[2][4];
                uint32_t bk = b_base + (uint32_t)ks * 32;
#pragma unroll
                for (int u2 = 0; u2 < 2; u2++) {
                    uint32_t tmp[4];
                    LDSM_X4(tmp, bk + (uint32_t)(u2 * 16) * PITCHB);
                    bh[2*u2][0] = tmp[0]; bh[2*u2][1] = tmp[1];
                    bh[2*u2+1][0] = tmp[2]; bh[2*u2+1][1] = tmp[3];
                    LDSM_X4(tmp, bk + PM_S + (uint32_t)(u2 * 16) * PITCHB);
                    bl[2*u2][0] = tmp[0]; bl[2*u2][1] = tmp[1];
                    bl[2*u2+1][0] = tmp[2]; bl[2*u2+1][1] = tmp[3];
                }
                uint32_t ak_ = a_base + (uint32_t)ks * 32;
#pragma unroll
                for (int mt = 0; mt < 2; mt++) {
                    LDSM_X4(ah[mt], ak_ + (uint32_t)(mt * 16) * PITCHB);
                    LDSM_X4(al[mt], ak_ + PM_S + (uint32_t)(mt * 16) * PITCHB);
                }
#pragma unroll
                for (int mt = 0; mt < 2; mt++)
#pragma unroll
                    for (int nt = 0; nt < 4; nt++) {
                        MMA_BF16(acc[mt][nt], ah[mt], bh[nt]);
                        MMA_BF16(acc[mt][nt], ah[mt], bl[nt]);
                        MMA_BF16(acc[mt][nt], al[mt], bh[nt]);
                    }
            }

            float* outp = (chunk == 0) ? g_q : (chunk == 1) ? g_k : g_v;
#pragma unroll
            for (int mt = 0; mt < 2; mt++)
#pragma unroll
                for (int rh = 0; rh < 2; rh++) {
                    int row = nb + wm * 32 + mt * 16 + g + rh * 8;
                    if (row < n) {
#pragma unroll
                        for (int nt = 0; nt < 4; nt++) {
                            int col = wn * 32 + nt * 8 + t4 * 2;
                            *(float2*)&outp[(size_t)row * HC + col] =
                                make_float2(acc[mt][nt][rh*2], acc[mt][nt][rh*2+1]);
                        }
                    }
                }
        }
    }
}

// ---------------------------------------------------------------------------
// Edge kernel (unchanged — validated, stays in profiled slot 4)
// ---------------------------------------------------------------------------
__global__ __launch_bounds__(512, 1) void k_edge_mma(
    const float* __restrict__ paired, const float* __restrict__ Wb,
    const int* __restrict__ qidx, const int* __restrict__ kidx,
    float* __restrict__ out_logit, int m)
{
    extern __shared__ char smem[];
    uint32_t sbase = smem_u32(smem);

    int tid  = threadIdx.x;
    int warp = tid >> 5;
    int lane = tid & 31;
    int wm   = warp >> 2;
    int wn   = warp & 3;
    int g    = lane >> 2;
    int t4   = lane & 3;

    int*   s_qi   = (int*)(smem + SM_QI);
    int*   s_ki   = (int*)(smem + SM_KI);
    float* s_part = (float*)(smem + SM_PART);

    for (int i = tid; i < 2 * 128 * 64; i += 512) {
        int kp = i & 63;
        int nc = (i >> 6) & 127;
        int p  = i >> 13;
        int wn_ = nc >> 5, ln = nc & 31;
        int u = ln >> 4, bias = (ln >> 3) & 1, off = ln & 7;
        int ch   = p * 64 + wn_ * 16 + u * 8 + off;
        int wcol = bias * 128 + ch;
        float2 w = make_float2(Wb[(2 * kp)     * COLS + wcol],
                               Wb[(2 * kp + 1) * COLS + wcol]);
        size_t off_b = (size_t)p * SM_WB_P + (size_t)nc * PITCHB + (size_t)kp * 4;
        split_store(smem + SM_WB + off_b, smem + SM_WB + SM_WB_S + off_b, w);
    }

    uint32_t aoff = (uint32_t)(((lane & 7) + 8 * ((lane >> 3) & 1)) * PITCHB
                               + ((lane >> 4) & 1) * 16);
    uint32_t boff = (uint32_t)(((lane & 7) + 8 * ((lane >> 4) & 1)) * PITCHB
                               + ((lane >> 3) & 1) * 16);
    uint32_t a_base = sbase + SM_A  + (uint32_t)(wm * 32) * PITCHB + aoff;
    uint32_t b_base = sbase + SM_WB + (uint32_t)(wn * 32) * PITCHB + boff;

    int ntiles = (m + TM - 1) / TM;
    for (int tile = blockIdx.x; tile < ntiles; tile += gridDim.x) {
        int ebase = tile * TM;
        __syncthreads();

        for (int i = tid; i < TM * 64; i += 512) {
            int r = i >> 6, cp = i & 63;
            int e = ebase + r;
            float2 x = (e < m) ? ((const float2*)paired)[(size_t)e * 64 + cp]
                               : make_float2(0.f, 0.f);
            size_t off_a = (size_t)r * PITCHB + (size_t)cp * 4;
            split_store(smem + SM_A + off_a, smem + SM_A + SM_A_S + off_a, x);
        }
        if (tid < TM) {
            int e = ebase + tid;
            s_qi[tid] = (e < m) ? qidx[e] : 0;
            s_ki[tid] = (e < m) ? kidx[e] : 0;
        }
        __syncthreads();

        float part[4][2];
#pragma unroll
        for (int a = 0; a < 4; a++) { part[a][0] = 0.f; part[a][1] = 0.f; }

#pragma unroll
        for (int p = 0; p < 2; p++) {
            float acc[2][4][4];
#pragma unroll
            for (int mt = 0; mt < 2; mt++)
#pragma unroll
                for (int nt = 0; nt < 4; nt++)
#pragma unroll
                    for (int el = 0; el < 4; el++) acc[mt][nt][el] = 0.f;

#pragma unroll 2
            for (int ks = 0; ks < 8; ks++) {
                uint32_t bh[4][2], bl[4][2], ah[2][4], al[2][4];
                uint32_t bk = b_base + (uint32_t)p * SM_WB_P + (uint32_t)ks * 32;
#pragma unroll
                for (int u2 = 0; u2 < 2; u2++) {
                    uint32_t tmp[4];
                    LDSM_X4(tmp, bk + (uint32_t)(u2 * 16) * PITCHB);
                    bh[2*u2][0] = tmp[0]; bh[2*u2][1] = tmp[1];
                    bh[2*u2+1][0] = tmp[2]; bh[2*u2+1][1] = tmp[3];
                    LDSM_X4(tmp, bk + SM_WB_S + (uint32_t)(u2 * 16) * PITCHB);
                    bl[2*u2][0] = tmp[0]; bl[2*u2][1] = tmp[1];
                    bl[2*u2+1][0] = tmp[2]; bl[2*u2+1][1] = tmp[3];
                }
                uint32_t ak_ = a_base + (uint32_t)ks * 32;
#pragma unroll
                for (int mt = 0; mt < 2; mt++) {
                    LDSM_X4(ah[mt], ak_ + (uint32_t)(mt * 16) * PITCHB);
                    LDSM_X4(al[mt], ak_ + SM_A_S + (uint32_t)(mt * 16) * PITCHB);
                }
#pragma unroll
                for (int mt = 0; mt < 2; mt++)
#pragma unroll
                    for (int nt = 0; nt < 4; nt++) {
                        MMA_BF16(acc[mt][nt], ah[mt], bh[nt]);
                        MMA_BF16(acc[mt][nt], ah[mt], bl[nt]);
                        MMA_BF16(acc[mt][nt], al[mt], bh[nt]);
                    }
            }

#pragma unroll
            for (int mt = 0; mt < 2; mt++)
#pragma unroll
                for (int rh = 0; rh < 2; rh++) {
                    int eli = wm * 32 + mt * 16 + g + rh * 8;
                    const float* qrow = g_q + (size_t)s_qi[eli] * HC;
                    const float* krow = g_k + (size_t)s_ki[eli] * HC;
#pragma unroll
                    for (int u = 0; u < 2; u++) {
                        int c = p * 64 + wn * 16 + u * 8 + t4 * 2;
                        float2 q2 = *(const float2*)(qrow + c);
                        float2 k2 = *(const float2*)(krow + c);
                        float bm0 = acc[mt][2*u][rh*2],   bm1 = acc[mt][2*u][rh*2+1];
                        float ba0 = acc[mt][2*u+1][rh*2], ba1 = acc[mt][2*u+1][rh*2+1];
                        float qk0 = q2.x * k2.x;
                        float qk1 = q2.y * k2.y;
                        part[mt*2+rh][0] += fmaf(qk0, bm0, qk0) + q2.x * ba0;
                        part[mt*2+rh][1] += fmaf(qk1, bm1, qk1) + q2.y * ba1;
                    }
                }
        }

#pragma unroll
        for (int mt = 0; mt < 2; mt++)
#pragma unroll
            for (int rh = 0; rh < 2; rh++) {
                int eli = wm * 32 + mt * 16 + g + rh * 8;
                float2* sp = (float2*)&s_part[wn * 1024 + eli * 8 + t4 * 2];
                *sp = make_float2(part[mt*2+rh][0], part[mt*2+rh][1]);
            }
        __syncthreads();

#pragma unroll
        for (int j = 0; j < 2; j++) {
            int i  = tid + j * 512;
            int el = i >> 3, h = i & 7;
            int e  = ebase + el;
            if (e < m) {
                float lg = (s_part[i] + s_part[1024 + i])
                         + (s_part[2048 + i] + s_part[3072 + i]);
                out_logit[e * NH + h] = lg;
                atomicMaxFloat(&g_segmax[s_qi[el] * NH + h], lg);
            }
        }
    }
}

// ---------------------------------------------------------------------------
// exp + denom accumulation (float4 over 4 heads)
// ---------------------------------------------------------------------------
__global__ void k_exp(const int* __restrict__ qidx,
                      const float* __restrict__ logit, int m)
{
    int i = blockIdx.x * blockDim.x + threadIdx.x;
    if (i >= m * 2) return;
    int e = i >> 1, half = (i & 1) << 2;
    int qi = qidx[e];
    float4 lg = ((const float4*)logit)[i];
    float4 mx = *(const float4*)&g_segmax[qi * NH + half];
    float4 ex = make_float4(expf(lg.x - mx.x), expf(lg.y - mx.y),
                            expf(lg.z - mx.z), expf(lg.w - mx.w));
    ((float4*)g_ex)[i] = ex;
    atomicAdd((float4*)&g_denom[qi * NH + half], ex);
}

// ---------------------------------------------------------------------------
// CSR aggregation (pull): agg[node][c] = sum_e ex[e][c%8]*v[ki[e]][c] / denom
// One 128-thread block per node; empty nodes write 0 (matches segment_sum).
// ---------------------------------------------------------------------------
__global__ __launch_bounds__(128) void k_agg(const int* __restrict__ kidx, int n)
{
    __shared__ int s_e[512];
    int node = blockIdx.x;
    if (node >= n) return;
    int c = threadIdx.x;
    int h = c & 7;

    int s = g_rows[node];
    int t = g_rows[node + 1];

    if (t <= s) {  // empty segment: agg = 0 (no NaN from 0/0)
        g_agg[(size_t)node * HC + c] = 0.0f;
        return;
    }

    float acc = 0.0f;
    for (int base = s; base < t; base += 512) {
        int cnt = t - base; if (cnt > 512) cnt = 512;
        for (int j = c; j < cnt; j += 128) s_e[j] = g_elist[base + j];
        __syncthreads();
        for (int j = 0; j < cnt; j++) {
            int e  = s_e[j];
            float at = __ldg(&g_ex[e * NH + h]);
            float vv = __ldg(&g_v[(size_t)kidx[e] * HC + c]);
            acc += at * vv;
        }
        __syncthreads();
    }
    float dn = g_denom[node * NH + h];
    g_agg[(size_t)node * HC + c] = acc / dn;
}

// ---------------------------------------------------------------------------
// result = agg @ Wo via bf16 split-3 mma (validated)
// ---------------------------------------------------------------------------
__global__ __launch_bounds__(512, 1) void k_out_mma(
    const float* __restrict__ Wo, float* __restrict__ out, int n)
{
    extern __shared__ char smem[];
    uint32_t sbase = smem_u32(smem);

    int tid  = threadIdx.x;
    int warp = tid >> 5;
    int lane = tid & 31;
    int wm   = warp >> 2;
    int wn   = warp & 3;
    int g    = lane >> 2;
    int t4   = lane & 3;

    uint32_t aoff = (uint32_t)(((lane & 7) + 8 * ((lane >> 3) & 1)) * PITCHB
                               + ((lane >> 4) & 1) * 16);
    uint32_t boff = (uint32_t)(((lane & 7) + 8 * ((lane >> 4) & 1)) * PITCHB
                               + ((lane >> 3) & 1) * 16);
    uint32_t a_base = sbase + PM_A + (uint32_t)(wm * 32) * PITCHB + aoff;
    uint32_t b_base = sbase + PM_W + (uint32_t)(wn * 32) * PITCHB + boff;

    int ntiles = (n + TM - 1) / TM;
    for (int tile = blockIdx.x; tile < ntiles; tile += gridDim.x) {
        int nb = tile * TM;
        __syncthreads();

        for (int i = tid; i < TM * 64; i += 512) {
            int r = i >> 6, cp = i & 63;
            int row = nb + r;
            float2 x = (row < n) ? ((const float2*)g_agg)[(size_t)row * 64 + cp]
                                 : make_float2(0.f, 0.f);
            size_t off = (size_t)r * PITCHB + (size_t)cp * 4;
            split_store(smem + PM_A + off, smem + PM_A + PM_S + off, x);
        }
        for (int i = tid; i < 128 * 64; i += 512) {
            int nc = i >> 6, kp = i & 63;
            float2 w = make_float2(Wo[(2 * kp)     * HC + nc],
                                   Wo[(2 * kp + 1) * HC + nc]);
            size_t off = (size_t)nc * PITCHB + (size_t)kp * 4;
            split_store(smem + PM_W + off, smem + PM_W + PM_S + off, w);
        }
        __syncthreads();

        float acc[2][4][4];
#pragma unroll
        for (int mt = 0; mt < 2; mt++)
#pragma unroll
            for (int nt = 0; nt < 4; nt++)
#pragma unroll
                for (int el = 0; el < 4; el++) acc[mt][nt][el] = 0.f;

#pragma unroll 2
        for (int ks = 0; ks < 8; ks++) {
            uint32_t bh[4][2], bl[4][2], ah[2][4], al[2][4];
            uint32_t bk = b_base + (uint32_t)ks * 32;
#pragma unroll
            for (int u2 = 0; u2 < 2; u2++) {
                uint32_t tmp[4];
                LDSM_X4(tmp, bk + (uint32_t)(u2 * 16) * PITCHB);
                bh[2*u2][0] = tmp[0]; bh[2*u2][1] = tmp[1];
                bh[2*u2+1][0] = tmp[2]; bh[2*u2+1][1] = tmp[3];
                LDSM_X4(tmp, bk + PM_S + (uint32_t)(u2 * 16) * PITCHB);
                bl[2*u2][0] = tmp[0]; bl[2*u2][1] = tmp[1];
                bl[2*u2+1][0] = tmp[2]; bl[2*u2+1][1] = tmp[3];
            }
            uint32_t ak_ = a_base + (uint32_t)ks * 32;
#pragma unroll
            for (int mt = 0; mt < 2; mt++) {
                LDSM_X4(ah[mt], ak_ + (uint32_t)(mt * 16) * PITCHB);
                LDSM_X4(al[mt], ak_ + PM_S + (uint32_t)(mt * 16) * PITCHB);
            }
#pragma unroll
            for (int mt = 0; mt < 2; mt++)
#pragma unroll
                for (int nt = 0; nt < 4; nt++) {
                    MMA_BF16(acc[mt][nt], ah[mt], bh[nt]);
                    MMA_BF16(acc[mt][nt], ah[mt], bl[nt]);
                    MMA_BF16(acc[mt][nt], al[mt], bh[nt]);
                }
        }

#pragma unroll
        for (int mt = 0; mt < 2; mt++)
#pragma unroll
            for (int rh = 0; rh < 2; rh++) {
                int row = nb + wm * 32 + mt * 16 + g + rh * 8;
                if (row < n) {
#pragma unroll
                    for (int nt = 0; nt < 4; nt++) {
                        int col = wn * 32 + nt * 8 + t4 * 2;
                        *(float2*)&out[(size_t)row * HC + col] =
                            make_float2(acc[mt][nt][rh*2], acc[mt][nt][rh*2+1]);
                    }
                }
            }
    }
}

// ---------------------------------------------------------------------------
extern "C" void kernel_launch(void* const* d_in, const int* in_sizes, int n_in,
                              void* d_out, int out_size)
{
    const float* query  = (const float*)d_in[0];
    const float* key    = (const float*)d_in[1];
    const int*   qidx   = (const int*)  d_in[2];
    const int*   kidx   = (const int*)  d_in[3];
    const float* paired = (const float*)d_in[4];
    const float* Wq     = (const float*)d_in[5];
    const float* Wkv    = (const float*)d_in[6];
    const float* Wb     = (const float*)d_in[7];
    const float* Wo     = (const float*)d_in[8];

    int n = in_sizes[0] / HC;   // 50000
    int m = in_sizes[2];        // 400000

    float* out_result = (float*)d_out;           // n*HC
    float* out_logit  = (float*)d_out + n * HC;  // m*NH

    cudaFuncSetAttribute(k_edge_mma, cudaFuncAttributeMaxDynamicSharedMemorySize,
                         SM_EDGE_TOTAL);
    cudaFuncSetAttribute(k_proj_mma, cudaFuncAttributeMaxDynamicSharedMemorySize,
                         PM_TOTAL);
    cudaFuncSetAttribute(k_out_mma, cudaFuncAttributeMaxDynamicSharedMemorySize,
                         PM_TOTAL);

    int dev = 0, nsm = 148;
    cudaGetDevice(&dev);
    cudaDeviceGetAttribute(&nsm, cudaDevAttrMultiProcessorCount, dev);

    int etiles = (m + TM - 1) / TM;
    int egrid  = etiles < nsm ? etiles : nsm;
    int ptiles = (n + TM - 1) / TM;
    int pgrid  = ptiles < nsm ? ptiles : nsm;
    int nscan  = (n + 255) / 256;

    // k_edge_mma must stay the 4th launch (profiled slot).
    k_init<<<(n * NH + 255) / 256, 256>>>(n);                            // 1
    k_proj_mma<<<pgrid, 512, PM_TOTAL>>>(query, key, Wq, Wkv, n);        // 2
    k_hist<<<(m + 255) / 256, 256>>>(qidx, m);                           // 3
    k_edge_mma<<<egrid, 512, SM_EDGE_TOTAL>>>(paired, Wb, qidx, kidx,    // 4
                                              out_logit, m);
    k_scan1<<<nscan, 256>>>(n);                                          // 5
    k_scan2<<<1, 256>>>(nscan);                                          // 6
    k_scan3<<<(n + 255) / 256, 256>>>(n, m);                             // 7
    k_fill<<<(m + 255) / 256, 256>>>(qidx, m);                           // 8
    k_exp<<<(m * 2 + 255) / 256, 256>>>(qidx, out_logit, m);             // 9
    k_agg<<<n, 128>>>(kidx, n);                                          // 10
    k_out_mma<<<pgrid, 512, PM_TOTAL>>>(Wo, out_result, n);              // 11
}

// round 9
// speedup vs baseline: 1.1450x; 1.1450x over previous
#include <cuda_runtime.h>
#include <cuda_bf16.h>
#include <math.h>
#include <stdint.h>

#define HC   128
#define NH   8
#define COLS 256
#define MAXN 50000
#define MAXM 400000
#define TM   128   // rows per tile

typedef unsigned long long ull;

// Scratch (device globals — no allocation allowed)
__device__ float g_q[MAXN * HC];
__device__ float g_k[MAXN * HC];
__device__ float g_v[MAXN * HC];
__device__ float g_agg[MAXN * HC];
__device__ float g_segmax[MAXN * NH];
__device__ float g_denom[MAXN * NH];
__device__ float g_ex[MAXM * NH];

__device__ __forceinline__ void atomicMaxFloat(float* addr, float val) {
    if (val >= 0.0f) atomicMax((int*)addr, __float_as_int(val));
    else             atomicMin((unsigned int*)addr, __float_as_uint(val));
}

__device__ __forceinline__ uint32_t smem_u32(const void* p) {
    uint32_t a;
    asm("{ .reg .u64 t; cvta.to.shared.u64 t, %1; cvt.u32.u64 %0, t; }"
        : "=r"(a) : "l"(p));
    return a;
}

// ---------------------------------------------------------------------------
// mma.sync / ldmatrix (base PTX ISA — valid for compute_103)
// ---------------------------------------------------------------------------
#define MMA_BF16(c, a, b) \
    asm volatile( \
        "mma.sync.aligned.m16n8k16.row.col.f32.bf16.bf16.f32 " \
        "{%0,%1,%2,%3}, {%4,%5,%6,%7}, {%8,%9}, {%0,%1,%2,%3};" \
        : "+f"((c)[0]), "+f"((c)[1]), "+f"((c)[2]), "+f"((c)[3]) \
        : "r"((a)[0]), "r"((a)[1]), "r"((a)[2]), "r"((a)[3]), \
          "r"((b)[0]), "r"((b)[1]))

#define LDSM_X4(r, addr) \
    asm volatile("ldmatrix.sync.aligned.m8n8.x4.shared.b16 {%0,%1,%2,%3}, [%4];" \
        : "=r"((r)[0]), "=r"((r)[1]), "=r"((r)[2]), "=r"((r)[3]) : "r"(addr))

// Row pitch 136 bf16 = 272 B (17x16B, conflict-free ldmatrix).
#define PITCHB  272
#define SPLIT_S 34816   // [128 rows][PITCHB] bytes: one split plane

__device__ __forceinline__ void split_store(char* hi_p, char* lo_p, float2 x) {
    __nv_bfloat162 hi2 = __floats2bfloat162_rn(x.x, x.y);
    float r0 = x.x - __bfloat162float(hi2.x);
    float r1 = x.y - __bfloat162float(hi2.y);
    __nv_bfloat162 lo2 = __floats2bfloat162_rn(r0, r1);
    *(uint32_t*)hi_p = *(uint32_t*)&hi2;
    *(uint32_t*)lo_p = *(uint32_t*)&lo2;
}

// ---------------- SMEM layouts ----------------
// edge kernel (unchanged)
#define SM_WB   0
#define SM_WB_S 69632
#define SM_WB_P 34816
#define SM_A    139264
#define SM_A_S  34816
#define SM_PART 208896
#define SM_QI   225280
#define SM_KI   225792
#define SM_EDGE_TOTAL 226304
// proj/out kernels: two resident W buffers + A buffer, each [2 splits][128][PITCHB]
#define OM_W0   0
#define OM_W1   69632
#define OM_A    139264
#define OM_TOTAL 208896

// ---------------------------------------------------------------------------
// 128x128x128 split-3 MMA core: acc += A(smem) * B(smem)^T
// ---------------------------------------------------------------------------
__device__ __forceinline__ void mma_tile_128(
    float acc[2][4][4], uint32_t a_base, uint32_t b_base)
{
#pragma unroll
    for (int mt = 0; mt < 2; mt++)
#pragma unroll
        for (int nt = 0; nt < 4; nt++)
#pragma unroll
            for (int el = 0; el < 4; el++) acc[mt][nt][el] = 0.f;

#pragma unroll 2
    for (int ks = 0; ks < 8; ks++) {
        uint32_t bh[4][2], bl[4][2], ah[2][4], al[2][4];
        uint32_t bk = b_base + (uint32_t)ks * 32;
#pragma unroll
        for (int u2 = 0; u2 < 2; u2++) {
            uint32_t tmp[4];
            LDSM_X4(tmp, bk + (uint32_t)(u2 * 16) * PITCHB);
            bh[2*u2][0] = tmp[0]; bh[2*u2][1] = tmp[1];
            bh[2*u2+1][0] = tmp[2]; bh[2*u2+1][1] = tmp[3];
            LDSM_X4(tmp, bk + SPLIT_S + (uint32_t)(u2 * 16) * PITCHB);
            bl[2*u2][0] = tmp[0]; bl[2*u2][1] = tmp[1];
            bl[2*u2+1][0] = tmp[2]; bl[2*u2+1][1] = tmp[3];
        }
        uint32_t ak_ = a_base + (uint32_t)ks * 32;
#pragma unroll
        for (int mt = 0; mt < 2; mt++) {
            LDSM_X4(ah[mt], ak_ + (uint32_t)(mt * 16) * PITCHB);
            LDSM_X4(al[mt], ak_ + SPLIT_S + (uint32_t)(mt * 16) * PITCHB);
        }
#pragma unroll
        for (int mt = 0; mt < 2; mt++)
#pragma unroll
            for (int nt = 0; nt < 4; nt++) {
                MMA_BF16(acc[mt][nt], ah[mt], bh[nt]);
                MMA_BF16(acc[mt][nt], ah[mt], bl[nt]);
                MMA_BF16(acc[mt][nt], al[mt], bh[nt]);
            }
    }
}

__device__ __forceinline__ void store_acc_128(
    float acc[2][4][4], float* outp, int nb,
    int wm, int wn, int g, int t4, int n)
{
#pragma unroll
    for (int mt = 0; mt < 2; mt++)
#pragma unroll
        for (int rh = 0; rh < 2; rh++) {
            int row = nb + wm * 32 + mt * 16 + g + rh * 8;
            if (row < n) {
#pragma unroll
                for (int nt = 0; nt < 4; nt++) {
                    int col = wn * 32 + nt * 8 + t4 * 2;
                    *(float2*)&outp[(size_t)row * HC + col] =
                        make_float2(acc[mt][nt][rh*2], acc[mt][nt][rh*2+1]);
                }
            }
        }
}

// ---------------------------------------------------------------------------
// Init kernels
// ---------------------------------------------------------------------------
__global__ void k_init_max(int n) {
    int i = blockIdx.x * blockDim.x + threadIdx.x;
    if (i < n * NH) {
        ((unsigned int*)g_segmax)[i] = 0xFF800000u;  // -inf
        g_denom[i] = 0.0f;
    }
}
__global__ void k_init_agg(int n) {
    int i = blockIdx.x * blockDim.x + threadIdx.x;
    if (i < n * HC) g_agg[i] = 0.0f;
}

// ---------------------------------------------------------------------------
// Projections, weights-resident: pass 1 Wq -> g_q; pass 2 Wk+Wv -> g_k,g_v.
// ---------------------------------------------------------------------------
__global__ __launch_bounds__(512, 1) void k_proj_mma(
    const float* __restrict__ query, const float* __restrict__ key,
    const float* __restrict__ Wq, const float* __restrict__ Wkv, int n)
{
    extern __shared__ char smem[];
    uint32_t sbase = smem_u32(smem);

    int tid  = threadIdx.x;
    int warp = tid >> 5;
    int lane = tid & 31;
    int wm   = warp >> 2;
    int wn   = warp & 3;
    int g    = lane >> 2;
    int t4   = lane & 3;

    uint32_t aoff = (uint32_t)(((lane & 7) + 8 * ((lane >> 3) & 1)) * PITCHB
                               + ((lane >> 4) & 1) * 16);
    uint32_t boff = (uint32_t)(((lane & 7) + 8 * ((lane >> 4) & 1)) * PITCHB
                               + ((lane >> 3) & 1) * 16);
    uint32_t a_base = sbase + OM_A  + (uint32_t)(wm * 32) * PITCHB + aoff;
    uint32_t b0     = sbase + OM_W0 + (uint32_t)(wn * 32) * PITCHB + boff;
    uint32_t b1     = sbase + OM_W1 + (uint32_t)(wn * 32) * PITCHB + boff;

    int ntiles = (n + TM - 1) / TM;
    float acc[2][4][4];

    // ---- pass 1: Wq resident ----
    for (int i = tid; i < 128 * 64; i += 512) {
        int nc = i >> 6, kp = i & 63;
        float2 w = make_float2(Wq[(2 * kp)     * HC + nc],
                               Wq[(2 * kp + 1) * HC + nc]);
        size_t off = (size_t)nc * PITCHB + (size_t)kp * 4;
        split_store(smem + OM_W0 + off, smem + OM_W0 + SPLIT_S + off, w);
    }
    for (int tile = blockIdx.x; tile < ntiles; tile += gridDim.x) {
        int nb = tile * TM;
        __syncthreads();   // prev tile readers done / W staging visible
        for (int i = tid; i < TM * 64; i += 512) {
            int r = i >> 6, cp = i & 63;
            int row = nb + r;
            float2 x = (row < n) ? ((const float2*)query)[(size_t)row * 64 + cp]
                                 : make_float2(0.f, 0.f);
            size_t off = (size_t)r * PITCHB + (size_t)cp * 4;
            split_store(smem + OM_A + off, smem + OM_A + SPLIT_S + off, x);
        }
        __syncthreads();
        mma_tile_128(acc, a_base, b0);
        store_acc_128(acc, g_q, nb, wm, wn, g, t4, n);
    }

    // ---- pass 2: Wk + Wv resident, key staged once ----
    __syncthreads();   // all warps done reading W0
    for (int i = tid; i < 128 * 64; i += 512) {
        int nc = i >> 6, kp = i & 63;
        float2 wk = make_float2(Wkv[(2 * kp)     * COLS + nc],
                                Wkv[(2 * kp + 1) * COLS + nc]);
        float2 wv = make_float2(Wkv[(2 * kp)     * COLS + HC + nc],
                                Wkv[(2 * kp + 1) * COLS + HC + nc]);
        size_t off = (size_t)nc * PITCHB + (size_t)kp * 4;
        split_store(smem + OM_W0 + off, smem + OM_W0 + SPLIT_S + off, wk);
        split_store(smem + OM_W1 + off, smem + OM_W1 + SPLIT_S + off, wv);
    }
    for (int tile = blockIdx.x; tile < ntiles; tile += gridDim.x) {
        int nb = tile * TM;
        __syncthreads();
        for (int i = tid; i < TM * 64; i += 512) {
            int r = i >> 6, cp = i & 63;
            int row = nb + r;
            float2 x = (row < n) ? ((const float2*)key)[(size_t)row * 64 + cp]
                                 : make_float2(0.f, 0.f);
            size_t off = (size_t)r * PITCHB + (size_t)cp * 4;
            split_store(smem + OM_A + off, smem + OM_A + SPLIT_S + off, x);
        }
        __syncthreads();
        mma_tile_128(acc, a_base, b0);
        store_acc_128(acc, g_k, nb, wm, wn, g, t4, n);
        mma_tile_128(acc, a_base, b1);
        store_acc_128(acc, g_v, nb, wm, wn, g, t4, n);
    }
}

// ---------------------------------------------------------------------------
// Edge kernel (unchanged — validated, stays in profiled slot 4)
// ---------------------------------------------------------------------------
__global__ __launch_bounds__(512, 1) void k_edge_mma(
    const float* __restrict__ paired, const float* __restrict__ Wb,
    const int* __restrict__ qidx, const int* __restrict__ kidx,
    float* __restrict__ out_logit, int m)
{
    extern __shared__ char smem[];
    uint32_t sbase = smem_u32(smem);

    int tid  = threadIdx.x;
    int warp = tid >> 5;
    int lane = tid & 31;
    int wm   = warp >> 2;
    int wn   = warp & 3;
    int g    = lane >> 2;
    int t4   = lane & 3;

    int*   s_qi   = (int*)(smem + SM_QI);
    int*   s_ki   = (int*)(smem + SM_KI);
    float* s_part = (float*)(smem + SM_PART);

    for (int i = tid; i < 2 * 128 * 64; i += 512) {
        int kp = i & 63;
        int nc = (i >> 6) & 127;
        int p  = i >> 13;
        int wn_ = nc >> 5, ln = nc & 31;
        int u = ln >> 4, bias = (ln >> 3) & 1, off = ln & 7;
        int ch   = p * 64 + wn_ * 16 + u * 8 + off;
        int wcol = bias * 128 + ch;
        float2 w = make_float2(Wb[(2 * kp)     * COLS + wcol],
                               Wb[(2 * kp + 1) * COLS + wcol]);
        size_t off_b = (size_t)p * SM_WB_P + (size_t)nc * PITCHB + (size_t)kp * 4;
        split_store(smem + SM_WB + off_b, smem + SM_WB + SM_WB_S + off_b, w);
    }

    uint32_t aoff = (uint32_t)(((lane & 7) + 8 * ((lane >> 3) & 1)) * PITCHB
                               + ((lane >> 4) & 1) * 16);
    uint32_t boff = (uint32_t)(((lane & 7) + 8 * ((lane >> 4) & 1)) * PITCHB
                               + ((lane >> 3) & 1) * 16);
    uint32_t a_base = sbase + SM_A  + (uint32_t)(wm * 32) * PITCHB + aoff;
    uint32_t b_base = sbase + SM_WB + (uint32_t)(wn * 32) * PITCHB + boff;

    int ntiles = (m + TM - 1) / TM;
    for (int tile = blockIdx.x; tile < ntiles; tile += gridDim.x) {
        int ebase = tile * TM;
        __syncthreads();

        for (int i = tid; i < TM * 64; i += 512) {
            int r = i >> 6, cp = i & 63;
            int e = ebase + r;
            float2 x = (e < m) ? ((const float2*)paired)[(size_t)e * 64 + cp]
                               : make_float2(0.f, 0.f);
            size_t off_a = (size_t)r * PITCHB + (size_t)cp * 4;
            split_store(smem + SM_A + off_a, smem + SM_A + SM_A_S + off_a, x);
        }
        if (tid < TM) {
            int e = ebase + tid;
            s_qi[tid] = (e < m) ? qidx[e] : 0;
            s_ki[tid] = (e < m) ? kidx[e] : 0;
        }
        __syncthreads();

        float part[4][2];
#pragma unroll
        for (int a = 0; a < 4; a++) { part[a][0] = 0.f; part[a][1] = 0.f; }

#pragma unroll
        for (int p = 0; p < 2; p++) {
            float acc[2][4][4];
#pragma unroll
            for (int mt = 0; mt < 2; mt++)
#pragma unroll
                for (int nt = 0; nt < 4; nt++)
#pragma unroll
                    for (int el = 0; el < 4; el++) acc[mt][nt][el] = 0.f;

#pragma unroll 2
            for (int ks = 0; ks < 8; ks++) {
                uint32_t bh[4][2], bl[4][2], ah[2][4], al[2][4];
                uint32_t bk = b_base + (uint32_t)p * SM_WB_P + (uint32_t)ks * 32;
#pragma unroll
                for (int u2 = 0; u2 < 2; u2++) {
                    uint32_t tmp[4];
                    LDSM_X4(tmp, bk + (uint32_t)(u2 * 16) * PITCHB);
                    bh[2*u2][0] = tmp[0]; bh[2*u2][1] = tmp[1];
                    bh[2*u2+1][0] = tmp[2]; bh[2*u2+1][1] = tmp[3];
                    LDSM_X4(tmp, bk + SM_WB_S + (uint32_t)(u2 * 16) * PITCHB);
                    bl[2*u2][0] = tmp[0]; bl[2*u2][1] = tmp[1];
                    bl[2*u2+1][0] = tmp[2]; bl[2*u2+1][1] = tmp[3];
                }
                uint32_t ak_ = a_base + (uint32_t)ks * 32;
#pragma unroll
                for (int mt = 0; mt < 2; mt++) {
                    LDSM_X4(ah[mt], ak_ + (uint32_t)(mt * 16) * PITCHB);
                    LDSM_X4(al[mt], ak_ + SM_A_S + (uint32_t)(mt * 16) * PITCHB);
                }
#pragma unroll
                for (int mt = 0; mt < 2; mt++)
#pragma unroll
                    for (int nt = 0; nt < 4; nt++) {
                        MMA_BF16(acc[mt][nt], ah[mt], bh[nt]);
                        MMA_BF16(acc[mt][nt], ah[mt], bl[nt]);
                        MMA_BF16(acc[mt][nt], al[mt], bh[nt]);
                    }
            }

#pragma unroll
            for (int mt = 0; mt < 2; mt++)
#pragma unroll
                for (int rh = 0; rh < 2; rh++) {
                    int eli = wm * 32 + mt * 16 + g + rh * 8;
                    const float* qrow = g_q + (size_t)s_qi[eli] * HC;
                    const float* krow = g_k + (size_t)s_ki[eli] * HC;
#pragma unroll
                    for (int u = 0; u < 2; u++) {
                        int c = p * 64 + wn * 16 + u * 8 + t4 * 2;
                        float2 q2 = *(const float2*)(qrow + c);
                        float2 k2 = *(const float2*)(krow + c);
                        float bm0 = acc[mt][2*u][rh*2],   bm1 = acc[mt][2*u][rh*2+1];
                        float ba0 = acc[mt][2*u+1][rh*2], ba1 = acc[mt][2*u+1][rh*2+1];
                        float qk0 = q2.x * k2.x;
                        float qk1 = q2.y * k2.y;
                        part[mt*2+rh][0] += fmaf(qk0, bm0, qk0) + q2.x * ba0;
                        part[mt*2+rh][1] += fmaf(qk1, bm1, qk1) + q2.y * ba1;
                    }
                }
        }

#pragma unroll
        for (int mt = 0; mt < 2; mt++)
#pragma unroll
            for (int rh = 0; rh < 2; rh++) {
                int eli = wm * 32 + mt * 16 + g + rh * 8;
                float2* sp = (float2*)&s_part[wn * 1024 + eli * 8 + t4 * 2];
                *sp = make_float2(part[mt*2+rh][0], part[mt*2+rh][1]);
            }
        __syncthreads();

#pragma unroll
        for (int j = 0; j < 2; j++) {
            int i  = tid + j * 512;
            int el = i >> 3, h = i & 7;
            int e  = ebase + el;
            if (e < m) {
                float lg = (s_part[i] + s_part[1024 + i])
                         + (s_part[2048 + i] + s_part[3072 + i]);
                out_logit[e * NH + h] = lg;
                atomicMaxFloat(&g_segmax[s_qi[el] * NH + h], lg);
            }
        }
    }
}

// ---------------------------------------------------------------------------
// exp + denom accumulation (float4 over 4 heads)
// ---------------------------------------------------------------------------
__global__ void k_exp(const int* __restrict__ qidx,
                      const float* __restrict__ logit, int m)
{
    int i = blockIdx.x * blockDim.x + threadIdx.x;
    if (i >= m * 2) return;
    int e = i >> 1, half = (i & 1) << 2;
    int qi = qidx[e];
    float4 lg = ((const float4*)logit)[i];
    float4 mx = *(const float4*)&g_segmax[qi * NH + half];
    float4 ex = make_float4(expf(lg.x - mx.x), expf(lg.y - mx.y),
                            expf(lg.z - mx.z), expf(lg.w - mx.w));
    ((float4*)g_ex)[i] = ex;
    atomicAdd((float4*)&g_denom[qi * NH + half], ex);
}

// ---------------------------------------------------------------------------
// scatter (normalization fused): agg[qi] += (ex/denom) * v[ki]
// ---------------------------------------------------------------------------
__global__ void k_scatter(const int* __restrict__ qidx,
                          const int* __restrict__ kidx, int m)
{
    int i = blockIdx.x * blockDim.x + threadIdx.x;
    if (i >= m * 32) return;
    int e  = i >> 5;
    int c4 = (i & 31) << 2;
    int qi = qidx[e];
    float4 v  = *(const float4*)&g_v[kidx[e] * HC + c4];
    float4 ex = *(const float4*)&g_ex[(e << 3) + (c4 & 7)];
    float4 dn = *(const float4*)&g_denom[qi * NH + (c4 & 7)];
    float4 val = make_float4((ex.x / dn.x) * v.x, (ex.y / dn.y) * v.y,
                             (ex.z / dn.z) * v.z, (ex.w / dn.w) * v.w);
    atomicAdd((float4*)&g_agg[qi * HC + c4], val);
}

// ---------------------------------------------------------------------------
// result = agg @ Wo, weights-resident
// ---------------------------------------------------------------------------
__global__ __launch_bounds__(512, 1) void k_out_mma(
    const float* __restrict__ Wo, float* __restrict__ out, int n)
{
    extern __shared__ char smem[];
    uint32_t sbase = smem_u32(smem);

    int tid  = threadIdx.x;
    int warp = tid >> 5;
    int lane = tid & 31;
    int wm   = warp >> 2;
    int wn   = warp & 3;
    int g    = lane >> 2;
    int t4   = lane & 3;

    uint32_t aoff = (uint32_t)(((lane & 7) + 8 * ((lane >> 3) & 1)) * PITCHB
                               + ((lane >> 4) & 1) * 16);
    uint32_t boff = (uint32_t)(((lane & 7) + 8 * ((lane >> 4) & 1)) * PITCHB
                               + ((lane >> 3) & 1) * 16);
    uint32_t a_base = sbase + OM_A  + (uint32_t)(wm * 32) * PITCHB + aoff;
    uint32_t b0     = sbase + OM_W0 + (uint32_t)(wn * 32) * PITCHB + boff;

    // stage Wo once
    for (int i = tid; i < 128 * 64; i += 512) {
        int nc = i >> 6, kp = i & 63;
        float2 w = make_float2(Wo[(2 * kp)     * HC + nc],
                               Wo[(2 * kp + 1) * HC + nc]);
        size_t off = (size_t)nc * PITCHB + (size_t)kp * 4;
        split_store(smem + OM_W0 + off, smem + OM_W0 + SPLIT_S + off, w);
    }

    int ntiles = (n + TM - 1) / TM;
    float acc[2][4][4];
    for (int tile = blockIdx.x; tile < ntiles; tile += gridDim.x) {
        int nb = tile * TM;
        __syncthreads();
        for (int i = tid; i < TM * 64; i += 512) {
            int r = i >> 6, cp = i & 63;
            int row = nb + r;
            float2 x = (row < n) ? ((const float2*)g_agg)[(size_t)row * 64 + cp]
                                 : make_float2(0.f, 0.f);
            size_t off = (size_t)r * PITCHB + (size_t)cp * 4;
            split_store(smem + OM_A + off, smem + OM_A + SPLIT_S + off, x);
        }
        __syncthreads();
        mma_tile_128(acc, a_base, b0);
        store_acc_128(acc, out, nb, wm, wn, g, t4, n);
    }
}

// ---------------------------------------------------------------------------
extern "C" void kernel_launch(void* const* d_in, const int* in_sizes, int n_in,
                              void* d_out, int out_size)
{
    const float* query  = (const float*)d_in[0];
    const float* key    = (const float*)d_in[1];
    const int*   qidx   = (const int*)  d_in[2];
    const int*   kidx   = (const int*)  d_in[3];
    const float* paired = (const float*)d_in[4];
    const float* Wq     = (const float*)d_in[5];
    const float* Wkv    = (const float*)d_in[6];
    const float* Wb     = (const float*)d_in[7];
    const float* Wo     = (const float*)d_in[8];

    int n = in_sizes[0] / HC;   // 50000
    int m = in_sizes[2];        // 400000

    float* out_result = (float*)d_out;           // n*HC
    float* out_logit  = (float*)d_out + n * HC;  // m*NH

    cudaFuncSetAttribute(k_edge_mma, cudaFuncAttributeMaxDynamicSharedMemorySize,
                         SM_EDGE_TOTAL);
    cudaFuncSetAttribute(k_proj_mma, cudaFuncAttributeMaxDynamicSharedMemorySize,
                         OM_TOTAL);
    cudaFuncSetAttribute(k_out_mma, cudaFuncAttributeMaxDynamicSharedMemorySize,
                         OM_TOTAL);

    int dev = 0, nsm = 148;
    cudaGetDevice(&dev);
    cudaDeviceGetAttribute(&nsm, cudaDevAttrMultiProcessorCount, dev);

    int etiles = (m + TM - 1) / TM;
    int egrid  = etiles < nsm ? etiles : nsm;
    int ptiles = (n + TM - 1) / TM;
    int pgrid  = ptiles < nsm ? ptiles : nsm;

    // k_edge_mma stays the 4th launch (profiled slot).
    k_init_max<<<(n * NH + 255) / 256, 256>>>(n);                        // 1
    k_proj_mma<<<pgrid, 512, OM_TOTAL>>>(query, key, Wq, Wkv, n);        // 2
    k_init_agg<<<(n * HC + 255) / 256, 256>>>(n);                        // 3
    k_edge_mma<<<egrid, 512, SM_EDGE_TOTAL>>>(paired, Wb, qidx, kidx,    // 4
                                              out_logit, m);
    k_exp<<<(m * 2 + 255) / 256, 256>>>(qidx, out_logit, m);             // 5
    k_scatter<<<(m * 32 + 255) / 256, 256>>>(qidx, kidx, m);             // 6
    k_out_mma<<<pgrid, 512, OM_TOTAL>>>(Wo, out_result, n);              // 7
}